// round 15
// baseline (speedup 1.0000x reference)
#include <cuda_runtime.h>
#include <cuda_bf16.h>
#include <cstdint>

#define J 21
#define D 128
#define BT 3                  // batch items per CTA -> 63 rows, pad to 64
#define THREADS 256
#define SB 136                // bf16 stride of activation tiles (272B rows)
#define CW 72                 // bf16 stride of weight chunk rows (144B rows)

#define OFF_X  0              // tokens -> x bf16 (GEMM A operand)        17408
#define OFF_Q  17408          // sQ -> sA (in place) -> sH0               17408
#define OFF_K  34816          // sK -> sH1                                17408
#define OFF_V  52224          // sV -> x delta (bf16)                     17408
#define OFF_B0 69632          // weight chunk buffer 0 (128x72x2)         18432
#define OFF_B1 88064          // weight chunk buffer 1                    18432
#define OFF_LN 106496         // 64 rows x 4 float2                        2048
#define SMEM_TOTAL 108544

// 16 weight chunks, each [128 n][64 k] bf16 packed (n*64+kk), 8192 elems.
// chunk c: tile t=c>>1 (0..7 = WqT,WkT,WvT,WoT,W1aT,W1bT,W2aT,W2bT), k-half h=c&1.
__device__ __align__(16) __nv_bfloat16 g_wt[131072];

__global__ void prep_weights(const float* __restrict__ Wq, const float* __restrict__ Wk,
                             const float* __restrict__ Wv, const float* __restrict__ Wo,
                             const float* __restrict__ W1, const float* __restrict__ W2) {
    int i = blockIdx.x * blockDim.x + threadIdx.x;
    if (i >= 131072) return;
    int c = i >> 13, j = i & 8191;
    int n = j >> 6, kk = j & 63;
    int t = c >> 1, k = (c & 1) * 64 + kk;
    float v;
    if (t < 4) {
        const float* W = (t == 0) ? Wq : (t == 1) ? Wk : (t == 2) ? Wv : Wo;
        v = W[k * 128 + n];
    } else if (t == 4) v = W1[k * 256 + n];
    else if (t == 5) v = W1[k * 256 + 128 + n];
    else if (t == 6) v = W2[k * 128 + n];
    else v = W2[(128 + k) * 128 + n];
    g_wt[i] = __float2bfloat16(v);
}

__device__ __forceinline__ uint32_t smem_u32(const void* p) {
    return (uint32_t)__cvta_generic_to_shared(p);
}

__device__ __forceinline__ void ldsm_x4(uint32_t* r, uint32_t addr) {
    asm volatile("ldmatrix.sync.aligned.m8n8.x4.shared.b16 {%0,%1,%2,%3}, [%4];\n"
                 : "=r"(r[0]), "=r"(r[1]), "=r"(r[2]), "=r"(r[3]) : "r"(addr));
}

__device__ __forceinline__ void stsm_x4(uint32_t addr, uint32_t r0, uint32_t r1,
                                        uint32_t r2, uint32_t r3) {
    asm volatile("stmatrix.sync.aligned.m8n8.x4.shared.b16 [%0], {%1,%2,%3,%4};\n"
                 :: "r"(addr), "r"(r0), "r"(r1), "r"(r2), "r"(r3) : "memory");
}

__device__ __forceinline__ void mma4(float* c, const uint32_t* a, uint32_t b0, uint32_t b1) {
    asm volatile(
        "mma.sync.aligned.m16n8k16.row.col.f32.bf16.bf16.f32 "
        "{%0,%1,%2,%3}, {%4,%5,%6,%7}, {%8,%9}, {%0,%1,%2,%3};\n"
        : "+f"(c[0]), "+f"(c[1]), "+f"(c[2]), "+f"(c[3])
        : "r"(a[0]), "r"(a[1]), "r"(a[2]), "r"(a[3]), "r"(b0), "r"(b1));
}

__device__ __forceinline__ uint32_t pack2(float x, float y) {
    __nv_bfloat162 t = __floats2bfloat162_rn(x, y);
    return *reinterpret_cast<uint32_t*>(&t);
}

// load 16 consecutive bf16 (16B-aligned) -> 16 floats
__device__ __forceinline__ void ld16bf(const __nv_bfloat16* p, float* f) {
    uint4 u0 = *(const uint4*)(p);
    uint4 u1 = *(const uint4*)(p + 8);
    uint32_t w[8] = {u0.x, u0.y, u0.z, u0.w, u1.x, u1.y, u1.z, u1.w};
#pragma unroll
    for (int i = 0; i < 8; i++) {
        float2 g = __bfloat1622float2(*(const __nv_bfloat162*)&w[i]);
        f[2 * i] = g.x;
        f[2 * i + 1] = g.y;
    }
}

// async prefetch of one [128 n][64 k] chunk into sW (stride CW), no wait
__device__ __forceinline__ void pf_c(const __nv_bfloat16* g, __nv_bfloat16* sW, int tid) {
#pragma unroll
    for (int i = tid; i < 1024; i += THREADS) {
        int n = i >> 3, u = (i & 7) * 8;
        asm volatile("cp.async.cg.shared.global [%0], [%1], 16;\n"
                     :: "r"(smem_u32(sW + n * CW + u)), "l"(g + n * 64 + u));
    }
    asm volatile("cp.async.commit_group;\n" ::: "memory");
}
#define WAITG(N) asm volatile("cp.async.wait_group %0;\n" :: "n"(N) : "memory")

// warp GEMM half with software-pipelined fragments:
// acc[M32 x N32] += A[M32 x k64 @ kbase] @ chunk^T
__device__ __forceinline__ void gemm_h(float* acc, const __nv_bfloat16* sA, int kbase,
                                       const __nv_bfloat16* sW,
                                       int lane, int mrow, int ncol) {
    const int la7 = lane & 7;
    const uint32_t a0A =
        smem_u32(sA + (mrow * 32 + la7 + (lane & 8)) * SB + kbase + ((lane & 16) ? 8 : 0));
    const uint32_t a1A = a0A + 16 * SB * 2;
    const uint32_t b0A =
        smem_u32(sW + (ncol * 32 + la7 + ((lane & 16) >> 1)) * CW + (lane & 8));
    const uint32_t b1A = b0A + 16 * CW * 2;
    uint32_t a0[2][4], a1[2][4], b0[2][4], b1[2][4];
    ldsm_x4(a0[0], a0A);
    ldsm_x4(b0[0], b0A);
    ldsm_x4(a1[0], a1A);
    ldsm_x4(b1[0], b1A);
#pragma unroll
    for (int ks = 0; ks < 64; ks += 16) {
        const int cur = (ks >> 4) & 1, nxt = cur ^ 1;
        if (ks < 48) {
            ldsm_x4(a0[nxt], a0A + (ks + 16) * 2);
            ldsm_x4(b0[nxt], b0A + (ks + 16) * 2);
            ldsm_x4(a1[nxt], a1A + (ks + 16) * 2);
            ldsm_x4(b1[nxt], b1A + (ks + 16) * 2);
        }
        mma4(acc + 0,  a0[cur], b0[cur][0], b0[cur][1]);
        mma4(acc + 4,  a0[cur], b0[cur][2], b0[cur][3]);
        mma4(acc + 8,  a0[cur], b1[cur][0], b1[cur][1]);
        mma4(acc + 12, a0[cur], b1[cur][2], b1[cur][3]);
        mma4(acc + 16, a1[cur], b0[cur][0], b0[cur][1]);
        mma4(acc + 20, a1[cur], b0[cur][2], b0[cur][3]);
        mma4(acc + 24, a1[cur], b1[cur][0], b1[cur][1]);
        mma4(acc + 28, a1[cur], b1[cur][2], b1[cur][3]);
    }
}

// paired warp GEMM half: two GEMMs sharing the SAME A fragments.
// A-fragments are software-pipelined; B loads stay adjacent to their MMAs.
__device__ __forceinline__ void gemm_pair(float* accP, float* accQ,
                                          const __nv_bfloat16* sA, int kbase,
                                          const __nv_bfloat16* sW0,
                                          const __nv_bfloat16* sW1,
                                          int lane, int mrow, int ncol) {
    const int la7 = lane & 7;
    const uint32_t a0A =
        smem_u32(sA + (mrow * 32 + la7 + (lane & 8)) * SB + kbase + ((lane & 16) ? 8 : 0));
    const uint32_t a1A = a0A + 16 * SB * 2;
    const uint32_t woff = (ncol * 32 + la7 + ((lane & 16) >> 1)) * CW + (lane & 8);
    const uint32_t p0A = smem_u32(sW0 + woff);
    const uint32_t p1A = p0A + 16 * CW * 2;
    const uint32_t q0A = smem_u32(sW1 + woff);
    const uint32_t q1A = q0A + 16 * CW * 2;
    uint32_t a0[2][4], a1[2][4];
    ldsm_x4(a0[0], a0A);
    ldsm_x4(a1[0], a1A);
#pragma unroll
    for (int ks = 0; ks < 64; ks += 16) {
        const int cur = (ks >> 4) & 1, nxt = cur ^ 1;
        uint32_t b0[4], b1[4];
        ldsm_x4(b0, p0A + ks * 2);
        ldsm_x4(b1, p1A + ks * 2);
        if (ks < 48) {
            ldsm_x4(a0[nxt], a0A + (ks + 16) * 2);
            ldsm_x4(a1[nxt], a1A + (ks + 16) * 2);
        }
        mma4(accP + 0,  a0[cur], b0[0], b0[1]);
        mma4(accP + 4,  a0[cur], b0[2], b0[3]);
        mma4(accP + 8,  a0[cur], b1[0], b1[1]);
        mma4(accP + 12, a0[cur], b1[2], b1[3]);
        mma4(accP + 16, a1[cur], b0[0], b0[1]);
        mma4(accP + 20, a1[cur], b0[2], b0[3]);
        mma4(accP + 24, a1[cur], b1[0], b1[1]);
        mma4(accP + 28, a1[cur], b1[2], b1[3]);
        ldsm_x4(b0, q0A + ks * 2);
        ldsm_x4(b1, q1A + ks * 2);
        mma4(accQ + 0,  a0[cur], b0[0], b0[1]);
        mma4(accQ + 4,  a0[cur], b0[2], b0[3]);
        mma4(accQ + 8,  a0[cur], b1[0], b1[1]);
        mma4(accQ + 12, a0[cur], b1[2], b1[3]);
        mma4(accQ + 16, a1[cur], b0[0], b0[1]);
        mma4(accQ + 20, a1[cur], b0[2], b0[3]);
        mma4(accQ + 24, a1[cur], b1[0], b1[1]);
        mma4(accQ + 28, a1[cur], b1[2], b1[3]);
    }
}
#define ACCI(t, ni) (((t) >> 1) * 16 + (ni) * 4 + ((t) & 1) * 2)

// epilogue via stmatrix: +bias (optional relu), store bf16 tile M32xN32
__device__ __forceinline__ void epi_sm(const float* acc, const float* __restrict__ bias,
                                       __nv_bfloat16* dst, int mrow, int ncol, int q2,
                                       int lane, bool relu) {
    const uint32_t abase = smem_u32(dst + (mrow * 32 + (lane & 7)) * SB
                                    + ncol * 32 + (lane >> 3) * 8);
#pragma unroll
    for (int t = 0; t < 4; t++) {
        uint32_t r[4];
#pragma unroll
        for (int m = 0; m < 4; m++) {
            int c = ncol * 32 + m * 8 + q2;
            const float* a = acc + ACCI(t, m);
            float v0 = a[0] + bias[c], v1 = a[1] + bias[c + 1];
            if (relu) { v0 = fmaxf(v0, 0.f); v1 = fmaxf(v1, 0.f); }
            r[m] = pack2(v0, v1);
        }
        stsm_x4(abase + (uint32_t)(t * 8 * SB * 2), r[0], r[1], r[2], r[3]);
    }
}

// epilogue with preloaded bias values bv8[8] (cols ncol*32 + ni*8 + q2 + {0,1})
__device__ __forceinline__ void epi_sm_r(const float* acc, const float* bv8,
                                         __nv_bfloat16* dst, int mrow, int ncol,
                                         int lane, bool relu) {
    const uint32_t abase = smem_u32(dst + (mrow * 32 + (lane & 7)) * SB
                                    + ncol * 32 + (lane >> 3) * 8);
#pragma unroll
    for (int t = 0; t < 4; t++) {
        uint32_t r[4];
#pragma unroll
        for (int m = 0; m < 4; m++) {
            const float* a = acc + ACCI(t, m);
            float v0 = a[0] + bv8[2 * m], v1 = a[1] + bv8[2 * m + 1];
            if (relu) { v0 = fmaxf(v0, 0.f); v1 = fmaxf(v1, 0.f); }
            r[m] = pack2(v0, v1);
        }
        stsm_x4(abase + (uint32_t)(t * 8 * SB * 2), r[0], r[1], r[2], r[3]);
    }
}

__global__ __launch_bounds__(THREADS, 2) void gat_fused_kernel(
    const float* __restrict__ tokens,
    const float* __restrict__ bq, const float* __restrict__ bk, const float* __restrict__ bv,
    const float* __restrict__ bo,
    const float* __restrict__ g1, const float* __restrict__ be1,
    const float* __restrict__ g2, const float* __restrict__ be2,
    const float* __restrict__ bf1, const float* __restrict__ bf2,
    float* __restrict__ out, int nBatch) {
    extern __shared__ char smem[];
    __nv_bfloat16* sXb = (__nv_bfloat16*)(smem + OFF_X);
    __nv_bfloat16* sQ = (__nv_bfloat16*)(smem + OFF_Q);
    __nv_bfloat16* sK = (__nv_bfloat16*)(smem + OFF_K);
    __nv_bfloat16* sV = (__nv_bfloat16*)(smem + OFF_V);
    __nv_bfloat16* sA = (__nv_bfloat16*)(smem + OFF_Q);     // in-place over sQ
    __nv_bfloat16* sB0 = (__nv_bfloat16*)(smem + OFF_B0);
    __nv_bfloat16* sB1 = (__nv_bfloat16*)(smem + OFF_B1);
    __nv_bfloat16* sH0 = (__nv_bfloat16*)(smem + OFF_Q);    // FF hidden 0-127
    __nv_bfloat16* sH1 = (__nv_bfloat16*)(smem + OFF_K);    // FF hidden 128-255
    __nv_bfloat16* sXD = (__nv_bfloat16*)(smem + OFF_V);    // x delta (over V)
    float2* sLN = (float2*)(smem + OFF_LN);

    const int tid = threadIdx.x;
    const int warp = tid >> 5;
    const int lane = tid & 31;
    const int mrow = warp >> 2;            // 0..1
    const int ncol = warp & 3;             // 0..3
    const int rbase = mrow * 32 + (lane >> 2);
    const int q2 = (lane & 3) * 2;
    const int cb = ncol * 32 + q2;         // this thread's base column (+ni*8)

    const int item0 = blockIdx.x * BT;
    const int nItems = min(BT, nBatch - item0);
    const int nRows = nItems * J;

    // prologue: chunks c0 (Wq h0) -> B0, c2 (Wk h0) -> B1; tokens -> bf16
    pf_c(g_wt, sB0, tid);
    pf_c(g_wt + 2 * 8192, sB1, tid);
    {
        const float* tp = tokens + (size_t)item0 * (J * D);
        for (int i = tid; i < 2048; i += THREADS) {
            int r = i >> 5, c4 = (i & 31) * 4;
            float4 v = make_float4(0.f, 0.f, 0.f, 0.f);
            if (r < nRows) v = *(const float4*)(tp + r * D + c4);
            uint2 u;
            u.x = pack2(v.x, v.y);
            u.y = pack2(v.z, v.w);
            *(uint2*)(sXb + r * SB + c4) = u;
        }
    }

    float accq[32], acck[32];

    // ============ Phase P1: paired (Q, K) GEMMs sharing A fragments ============
#pragma unroll
    for (int i = 0; i < 32; i++) { accq[i] = 0.f; acck[i] = 0.f; }
    WAITG(0); __syncthreads();
    gemm_pair(accq, acck, sXb, 0, sB0, sB1, lane, mrow, ncol);
    __syncthreads();
    pf_c(g_wt + 1 * 8192, sB0, tid);   // Wq h1
    pf_c(g_wt + 3 * 8192, sB1, tid);   // Wk h1
    WAITG(0); __syncthreads();
    gemm_pair(accq, acck, sXb, 64, sB0, sB1, lane, mrow, ncol);
    __syncthreads();
    pf_c(g_wt + 4 * 8192, sB0, tid);   // Wv h0
    pf_c(g_wt + 5 * 8192, sB1, tid);   // Wv h1
    epi_sm(accq, bq, sQ, mrow, ncol, q2, lane, false);
    epi_sm(acck, bk, sK, mrow, ncol, q2, lane, false);
    // zero pad rows of sQ/sA (attention never writes them)
    for (int i = tid + nRows * 16; i < 64 * 16; i += THREADS) {
        int r = i >> 4, u = (i & 15) * 8;
        *(uint4*)(sA + r * SB + u) = make_uint4(0u, 0u, 0u, 0u);
    }

    // ============ Phase P2: V — preload bv, both halves back-to-back ============
    {
        float bvr[8];
#pragma unroll
        for (int m = 0; m < 4; m++) {
            float2 b = *(const float2*)(bv + cb + m * 8);
            bvr[2 * m] = b.x; bvr[2 * m + 1] = b.y;
        }
#pragma unroll
        for (int i = 0; i < 32; i++) accq[i] = 0.f;
        WAITG(0); __syncthreads();         // Wv h0,h1 ready
        gemm_h(accq, sXb, 0, sB0, lane, mrow, ncol);
        gemm_h(accq, sXb, 64, sB1, lane, mrow, ncol);
        __syncthreads();                   // all B0/B1 reads done
        pf_c(g_wt + 6 * 8192, sB0, tid);   // Wo h0 (covered by attention)
        pf_c(g_wt + 7 * 8192, sB1, tid);   // Wo h1
        epi_sm_r(accq, bvr, sV, mrow, ncol, lane, false);
    }
    __syncthreads();                   // Q,K,V visible for attention

    // ====== Phase B: sparse masked attention — joint-major task order ======
    for (int task = tid; task < nItems * 168; task += THREADS) {
        const int it = task / 168;
        const int rem = task - it * 168;
        const int qi = rem >> 3;
        const int hd = rem & 7;
        const int rb = it * J;
        const int hb = hd * 16;

        float qv[16];
        ld16bf(sQ + (rb + qi) * SB + hb, qv);

        const int p = (qi - 1) & 3;
        const int cnt = (qi == 0) ? 6 : ((p == 3) ? 2 : 3);

        float av[16];
#pragma unroll
        for (int i = 0; i < 16; i++) av[i] = 0.f;
        float sum = 0.f;
#pragma unroll
        for (int n = 0; n < 6; n++) {
            if (n < cnt) {
                int kj;
                if (qi == 0) kj = (n == 0) ? 0 : 4 * n - 3;
                else kj = (n == 0) ? ((p == 0) ? 0 : qi - 1) : ((n == 1) ? qi : qi + 1);

                float kv[16];
                ld16bf(sK + (rb + kj) * SB + hb, kv);
                float d = 0.f;
#pragma unroll
                for (int i = 0; i < 16; i++) d = fmaf(qv[i], kv[i], d);
                float e = __expf(d * 0.25f);   // scores ~N(0,0.05): safe w/o max-sub
                sum += e;

                float vv[16];
                ld16bf(sV + (rb + kj) * SB + hb, vv);
#pragma unroll
                for (int i = 0; i < 16; i++) av[i] = fmaf(e, vv[i], av[i]);
            }
        }
        float inv = 1.f / sum;
        uint4 o0, o1;
        o0.x = pack2(av[0] * inv, av[1] * inv);   o0.y = pack2(av[2] * inv, av[3] * inv);
        o0.z = pack2(av[4] * inv, av[5] * inv);   o0.w = pack2(av[6] * inv, av[7] * inv);
        o1.x = pack2(av[8] * inv, av[9] * inv);   o1.y = pack2(av[10] * inv, av[11] * inv);
        o1.z = pack2(av[12] * inv, av[13] * inv); o1.w = pack2(av[14] * inv, av[15] * inv);
        __nv_bfloat16* arow = sA + (rb + qi) * SB + hb;     // in-place over own Q row
        *(uint4*)(arow) = o0;
        *(uint4*)(arow + 8) = o1;
    }

    // ===== Phase C: Wo — preload tokens residual + bo, GEMM halves, LN1 =====
    {
        float tokr[16], bor[8];
        {
            const bool ok0 = (rbase < nRows), ok1 = (rbase + 8 < nRows);
            const float* tok0 = tokens + ((size_t)item0 * J + rbase) * D;
            const float* tok1 = tok0 + 8 * D;
#pragma unroll
            for (int m = 0; m < 4; m++) {
                float2 b = *(const float2*)(bo + cb + m * 8);
                bor[2 * m] = b.x; bor[2 * m + 1] = b.y;
                float2 t0 = ok0 ? *(const float2*)(tok0 + cb + m * 8) : make_float2(0.f, 0.f);
                float2 t1 = ok1 ? *(const float2*)(tok1 + cb + m * 8) : make_float2(0.f, 0.f);
                tokr[4 * m + 0] = t0.x; tokr[4 * m + 1] = t0.y;
                tokr[4 * m + 2] = t1.x; tokr[4 * m + 3] = t1.y;
            }
        }
#pragma unroll
        for (int i = 0; i < 32; i++) accq[i] = 0.f;
        WAITG(0); __syncthreads();     // Wo chunks ready; attention writes visible
        gemm_h(accq, sA, 0, sB0, lane, mrow, ncol);
        gemm_h(accq, sA, 64, sB1, lane, mrow, ncol);
        __syncthreads();               // B0/B1 reads done
        pf_c(g_wt + 8 * 8192, sB0, tid);    // W1a h0 (covered by LN1 epilogue)
        pf_c(g_wt + 10 * 8192, sB1, tid);   // W1b h0

        // rows t=0,1 (rbase, rbase+8) use preloaded tokr; rows t=2,3 load now
        const float* tok2 = tokens + ((size_t)item0 * J + rbase + 16) * D;
        float s[4], ss[4];
#pragma unroll
        for (int t = 0; t < 4; t++) {
            int R = rbase + t * 8;
            const bool okr = R < nRows;
            s[t] = 0.f; ss[t] = 0.f;
#pragma unroll
            for (int ni = 0; ni < 4; ni++) {
                int c = cb + ni * 8;
                float* a = accq + ACCI(t, ni);
                float tk0, tk1;
                if (t < 2) {
                    tk0 = tokr[4 * ni + 2 * t];
                    tk1 = tokr[4 * ni + 2 * t + 1];
                } else {
                    float2 tk = okr ? *(const float2*)(tok2 + (t - 2) * 8 * D + c)
                                    : make_float2(0.f, 0.f);
                    tk0 = tk.x; tk1 = tk.y;
                }
                float v0 = a[0] + bor[2 * ni] + tk0;
                float v1 = a[1] + bor[2 * ni + 1] + tk1;
                a[0] = v0; a[1] = v1;
                s[t] += v0 + v1;
                ss[t] += v0 * v0 + v1 * v1;
            }
        }
#pragma unroll
        for (int t = 0; t < 4; t++) {
            s[t] += __shfl_xor_sync(0xffffffffu, s[t], 1);
            s[t] += __shfl_xor_sync(0xffffffffu, s[t], 2);
            ss[t] += __shfl_xor_sync(0xffffffffu, ss[t], 1);
            ss[t] += __shfl_xor_sync(0xffffffffu, ss[t], 2);
        }
        if ((lane & 3) == 0) {
#pragma unroll
            for (int t = 0; t < 4; t++)
                sLN[(rbase + t * 8) * 4 + ncol] = make_float2(s[t], ss[t]);
        }
        __syncthreads();
        const uint32_t abase = (mrow * 32 + (lane & 7)) * SB + ncol * 32 + (lane >> 3) * 8;
#pragma unroll
        for (int t = 0; t < 4; t++) {
            int R = rbase + t * 8;
            float2 p0 = sLN[R * 4 + 0], p1 = sLN[R * 4 + 1];
            float2 p2 = sLN[R * 4 + 2], p3 = sLN[R * 4 + 3];
            float mu = (p0.x + p1.x + p2.x + p3.x) * (1.f / 128.f);
            float iv = rsqrtf((p0.y + p1.y + p2.y + p3.y) * (1.f / 128.f) - mu * mu + 1e-5f);
            uint32_t rm[4], rd[4];
#pragma unroll
            for (int ni = 0; ni < 4; ni++) {
                int c = cb + ni * 8;
                float* a = accq + ACCI(t, ni);
                float2 gg = *(const float2*)(g1 + c);
                float2 bb = *(const float2*)(be1 + c);
                float x0 = (a[0] - mu) * iv * gg.x + bb.x;
                float x1 = (a[1] - mu) * iv * gg.y + bb.y;
                __nv_bfloat162 m = __floats2bfloat162_rn(x0, x1);
                float2 f = __bfloat1622float2(m);
                rm[ni] = *(uint32_t*)&m;
                __nv_bfloat162 dl = __floats2bfloat162_rn(x0 - f.x, x1 - f.y);
                rd[ni] = *(uint32_t*)&dl;
            }
            uint32_t roff = abase + (uint32_t)(t * 8 * SB);
            stsm_x4(smem_u32(sXb + roff), rm[0], rm[1], rm[2], rm[3]);
            stsm_x4(smem_u32(sXD + roff), rd[0], rd[1], rd[2], rd[3]);
        }
    }

    // ============ Phase P5: paired (FF1a, FF1b) GEMMs sharing A fragments ============
#pragma unroll
    for (int i = 0; i < 32; i++) { accq[i] = 0.f; acck[i] = 0.f; }
    WAITG(0); __syncthreads();        // W1a/W1b h0 ready; sXb/sXD writes visible
    gemm_pair(accq, acck, sXb, 0, sB0, sB1, lane, mrow, ncol);
    __syncthreads();
    pf_c(g_wt + 9 * 8192, sB0, tid);    // W1a h1
    pf_c(g_wt + 11 * 8192, sB1, tid);   // W1b h1
    WAITG(0); __syncthreads();
    gemm_pair(accq, acck, sXb, 64, sB0, sB1, lane, mrow, ncol);
    __syncthreads();
    pf_c(g_wt + 12 * 8192, sB0, tid);   // W2a h0
    pf_c(g_wt + 13 * 8192, sB1, tid);   // W2a h1
    epi_sm(accq, bf1, sH0, mrow, ncol, q2, lane, true);
    epi_sm(acck, bf1 + 128, sH1, mrow, ncol, q2, lane, true);

    // ===== Phase E: FF2 = H0*W2a + H1*W2b + residual + LN2 =====
    {
#pragma unroll
        for (int i = 0; i < 32; i++) accq[i] = 0.f;
        WAITG(0); __syncthreads();     // W2a ready; H writes visible
        gemm_h(accq, sH0, 0, sB0, lane, mrow, ncol);
        __syncthreads();               // B0 reads done
        pf_c(g_wt + 14 * 8192, sB0, tid);   // W2b h0 (covered by next gemm)
        gemm_h(accq, sH0, 64, sB1, lane, mrow, ncol);
        __syncthreads();               // B1 reads done
        pf_c(g_wt + 15 * 8192, sB1, tid);   // W2b h1
        float bf2r[8];
#pragma unroll
        for (int m = 0; m < 4; m++) {
            float2 b = *(const float2*)(bf2 + cb + m * 8);
            bf2r[2 * m] = b.x; bf2r[2 * m + 1] = b.y;
        }
        WAITG(1); __syncthreads();     // W2b h0 done
        gemm_h(accq, sH1, 0, sB0, lane, mrow, ncol);
        WAITG(0); __syncthreads();     // W2b h1 done
        gemm_h(accq, sH1, 64, sB1, lane, mrow, ncol);

        float s[4], ss[4];
#pragma unroll
        for (int t = 0; t < 4; t++) {
            int R = rbase + t * 8;
            s[t] = 0.f; ss[t] = 0.f;
#pragma unroll
            for (int ni = 0; ni < 4; ni++) {
                int c = cb + ni * 8;
                float* a = accq + ACCI(t, ni);
                float2 xb = __bfloat1622float2(*(__nv_bfloat162*)(sXb + R * SB + c));
                float2 xd = __bfloat1622float2(*(__nv_bfloat162*)(sXD + R * SB + c));
                float v0 = a[0] + bf2r[2 * ni] + xb.x + xd.x;
                float v1 = a[1] + bf2r[2 * ni + 1] + xb.y + xd.y;
                a[0] = v0; a[1] = v1;
                s[t] += v0 + v1;
                ss[t] += v0 * v0 + v1 * v1;
            }
        }
#pragma unroll
        for (int t = 0; t < 4; t++) {
            s[t] += __shfl_xor_sync(0xffffffffu, s[t], 1);
            s[t] += __shfl_xor_sync(0xffffffffu, s[t], 2);
            ss[t] += __shfl_xor_sync(0xffffffffu, ss[t], 1);
            ss[t] += __shfl_xor_sync(0xffffffffu, ss[t], 2);
        }
        if ((lane & 3) == 0) {
#pragma unroll
            for (int t = 0; t < 4; t++)
                sLN[(rbase + t * 8) * 4 + ncol] = make_float2(s[t], ss[t]);
        }
        __syncthreads();
#pragma unroll
        for (int t = 0; t < 4; t++) {
            int R = rbase + t * 8;
            float2 p0 = sLN[R * 4 + 0], p1 = sLN[R * 4 + 1];
            float2 p2 = sLN[R * 4 + 2], p3 = sLN[R * 4 + 3];
            float mu = (p0.x + p1.x + p2.x + p3.x) * (1.f / 128.f);
            float iv = rsqrtf((p0.y + p1.y + p2.y + p3.y) * (1.f / 128.f) - mu * mu + 1e-5f);
            if (R < nRows) {
                float* orow = out + ((size_t)item0 * J + R) * D;
#pragma unroll
                for (int ni = 0; ni < 4; ni++) {
                    int c = cb + ni * 8;
                    const float* a = accq + ACCI(t, ni);
                    float2 gg = *(const float2*)(g2 + c);
                    float2 bb = *(const float2*)(be2 + c);
                    *(float2*)(orow + c) = make_float2((a[0] - mu) * iv * gg.x + bb.x,
                                                       (a[1] - mu) * iv * gg.y + bb.y);
                }
            }
        }
    }
}

extern "C" void kernel_launch(void* const* d_in, const int* in_sizes, int n_in,
                              void* d_out, int out_size) {
    const float* tokens = (const float*)d_in[0];
    const float* Wq = (const float*)d_in[1];  const float* bq = (const float*)d_in[2];
    const float* Wk = (const float*)d_in[3];  const float* bk = (const float*)d_in[4];
    const float* Wv = (const float*)d_in[5];  const float* bv = (const float*)d_in[6];
    const float* Wo = (const float*)d_in[7];  const float* bo = (const float*)d_in[8];
    const float* g1 = (const float*)d_in[9];  const float* be1 = (const float*)d_in[10];
    const float* g2 = (const float*)d_in[11]; const float* be2 = (const float*)d_in[12];
    const float* W1 = (const float*)d_in[13]; const float* bf1 = (const float*)d_in[14];
    const float* W2 = (const float*)d_in[15]; const float* bf2 = (const float*)d_in[16];
    float* out = (float*)d_out;

    int nBatch = in_sizes[0] / (J * D);
    int nCTA = (nBatch + BT - 1) / BT;

    cudaFuncSetAttribute(gat_fused_kernel, cudaFuncAttributeMaxDynamicSharedMemorySize,
                         SMEM_TOTAL);

    prep_weights<<<512, 256>>>(Wq, Wk, Wv, Wo, W1, W2);
    gat_fused_kernel<<<nCTA, THREADS, SMEM_TOTAL>>>(tokens, bq, bk, bv, bo, g1, be1,
                                                    g2, be2, bf1, bf2, out, nBatch);
}

// round 16
// speedup vs baseline: 1.0148x; 1.0148x over previous
#include <cuda_runtime.h>
#include <cuda_bf16.h>
#include <cstdint>

#define J 21
#define D 128
#define BT 3                  // batch items per CTA -> 63 rows, pad to 64
#define THREADS 256
#define SB 136                // bf16 stride of activation tiles (272B rows)
#define CW 72                 // bf16 stride of weight chunk rows (144B rows)

#define OFF_X  0              // tokens -> x bf16 (GEMM A operand)        17408
#define OFF_Q  17408          // sQ -> sA (in place) -> sH0               17408
#define OFF_K  34816          // sK -> sH1                                17408
#define OFF_V  52224          // sV -> x delta (bf16)                     17408
#define OFF_B0 69632          // weight chunk buffer 0 (128x72x2)         18432
#define OFF_B1 88064          // weight chunk buffer 1                    18432
#define OFF_LN 106496         // 64 rows x 4 float2                        2048
#define SMEM_TOTAL 108544

// 16 weight chunks, each [128 n][64 k] bf16 packed (n*64+kk), 8192 elems.
// chunk c: tile t=c>>1 (0..7 = WqT,WkT,WvT,WoT,W1aT,W1bT,W2aT,W2bT), k-half h=c&1.
__device__ __align__(16) __nv_bfloat16 g_wt[131072];

__global__ void prep_weights(const float* __restrict__ Wq, const float* __restrict__ Wk,
                             const float* __restrict__ Wv, const float* __restrict__ Wo,
                             const float* __restrict__ W1, const float* __restrict__ W2) {
    int i = blockIdx.x * blockDim.x + threadIdx.x;
    if (i >= 131072) return;
    int c = i >> 13, j = i & 8191;
    int n = j >> 6, kk = j & 63;
    int t = c >> 1, k = (c & 1) * 64 + kk;
    float v;
    if (t < 4) {
        const float* W = (t == 0) ? Wq : (t == 1) ? Wk : (t == 2) ? Wv : Wo;
        v = W[k * 128 + n];
    } else if (t == 4) v = W1[k * 256 + n];
    else if (t == 5) v = W1[k * 256 + 128 + n];
    else if (t == 6) v = W2[k * 128 + n];
    else v = W2[(128 + k) * 128 + n];
    g_wt[i] = __float2bfloat16(v);
}

__device__ __forceinline__ uint32_t smem_u32(const void* p) {
    return (uint32_t)__cvta_generic_to_shared(p);
}

__device__ __forceinline__ void ldsm_x4(uint32_t* r, uint32_t addr) {
    asm volatile("ldmatrix.sync.aligned.m8n8.x4.shared.b16 {%0,%1,%2,%3}, [%4];\n"
                 : "=r"(r[0]), "=r"(r[1]), "=r"(r[2]), "=r"(r[3]) : "r"(addr));
}

__device__ __forceinline__ void stsm_x4(uint32_t addr, uint32_t r0, uint32_t r1,
                                        uint32_t r2, uint32_t r3) {
    asm volatile("stmatrix.sync.aligned.m8n8.x4.shared.b16 [%0], {%1,%2,%3,%4};\n"
                 :: "r"(addr), "r"(r0), "r"(r1), "r"(r2), "r"(r3) : "memory");
}

__device__ __forceinline__ void mma4(float* c, const uint32_t* a, uint32_t b0, uint32_t b1) {
    asm volatile(
        "mma.sync.aligned.m16n8k16.row.col.f32.bf16.bf16.f32 "
        "{%0,%1,%2,%3}, {%4,%5,%6,%7}, {%8,%9}, {%0,%1,%2,%3};\n"
        : "+f"(c[0]), "+f"(c[1]), "+f"(c[2]), "+f"(c[3])
        : "r"(a[0]), "r"(a[1]), "r"(a[2]), "r"(a[3]), "r"(b0), "r"(b1));
}

__device__ __forceinline__ uint32_t pack2(float x, float y) {
    __nv_bfloat162 t = __floats2bfloat162_rn(x, y);
    return *reinterpret_cast<uint32_t*>(&t);
}

// load 16 consecutive bf16 (16B-aligned) -> 16 floats
__device__ __forceinline__ void ld16bf(const __nv_bfloat16* p, float* f) {
    uint4 u0 = *(const uint4*)(p);
    uint4 u1 = *(const uint4*)(p + 8);
    uint32_t w[8] = {u0.x, u0.y, u0.z, u0.w, u1.x, u1.y, u1.z, u1.w};
#pragma unroll
    for (int i = 0; i < 8; i++) {
        float2 g = __bfloat1622float2(*(const __nv_bfloat162*)&w[i]);
        f[2 * i] = g.x;
        f[2 * i + 1] = g.y;
    }
}

// async prefetch of one [128 n][64 k] chunk into sW (stride CW), no wait
__device__ __forceinline__ void pf_c(const __nv_bfloat16* g, __nv_bfloat16* sW, int tid) {
#pragma unroll
    for (int i = tid; i < 1024; i += THREADS) {
        int n = i >> 3, u = (i & 7) * 8;
        asm volatile("cp.async.cg.shared.global [%0], [%1], 16;\n"
                     :: "r"(smem_u32(sW + n * CW + u)), "l"(g + n * 64 + u));
    }
    asm volatile("cp.async.commit_group;\n" ::: "memory");
}
#define WAITG(N) asm volatile("cp.async.wait_group %0;\n" :: "n"(N) : "memory")

// warp GEMM half with software-pipelined fragments:
// acc[M32 x N32] += A[M32 x k64 @ kbase] @ chunk^T
__device__ __forceinline__ void gemm_h(float* acc, const __nv_bfloat16* sA, int kbase,
                                       const __nv_bfloat16* sW,
                                       int lane, int mrow, int ncol) {
    const int la7 = lane & 7;
    const uint32_t a0A =
        smem_u32(sA + (mrow * 32 + la7 + (lane & 8)) * SB + kbase + ((lane & 16) ? 8 : 0));
    const uint32_t a1A = a0A + 16 * SB * 2;
    const uint32_t b0A =
        smem_u32(sW + (ncol * 32 + la7 + ((lane & 16) >> 1)) * CW + (lane & 8));
    const uint32_t b1A = b0A + 16 * CW * 2;
    uint32_t a0[2][4], a1[2][4], b0[2][4], b1[2][4];
    ldsm_x4(a0[0], a0A);
    ldsm_x4(b0[0], b0A);
    ldsm_x4(a1[0], a1A);
    ldsm_x4(b1[0], b1A);
#pragma unroll
    for (int ks = 0; ks < 64; ks += 16) {
        const int cur = (ks >> 4) & 1, nxt = cur ^ 1;
        if (ks < 48) {
            ldsm_x4(a0[nxt], a0A + (ks + 16) * 2);
            ldsm_x4(b0[nxt], b0A + (ks + 16) * 2);
            ldsm_x4(a1[nxt], a1A + (ks + 16) * 2);
            ldsm_x4(b1[nxt], b1A + (ks + 16) * 2);
        }
        mma4(acc + 0,  a0[cur], b0[cur][0], b0[cur][1]);
        mma4(acc + 4,  a0[cur], b0[cur][2], b0[cur][3]);
        mma4(acc + 8,  a0[cur], b1[cur][0], b1[cur][1]);
        mma4(acc + 12, a0[cur], b1[cur][2], b1[cur][3]);
        mma4(acc + 16, a1[cur], b0[cur][0], b0[cur][1]);
        mma4(acc + 20, a1[cur], b0[cur][2], b0[cur][3]);
        mma4(acc + 24, a1[cur], b1[cur][0], b1[cur][1]);
        mma4(acc + 28, a1[cur], b1[cur][2], b1[cur][3]);
    }
}

// full-K warp GEMM: acc[M32 x N32] += A[M32 x K128] with k0-63 from chunk sW0
// and k64-127 from chunk sW1, one continuous software pipeline (no mid drain).
// FP accumulation order identical to gemm_h(k0,sW0); gemm_h(k64,sW1).
__device__ __forceinline__ void gemm_h2(float* acc, const __nv_bfloat16* sA,
                                        const __nv_bfloat16* sW0,
                                        const __nv_bfloat16* sW1,
                                        int lane, int mrow, int ncol) {
    const int la7 = lane & 7;
    const uint32_t a0A =
        smem_u32(sA + (mrow * 32 + la7 + (lane & 8)) * SB + ((lane & 16) ? 8 : 0));
    const uint32_t a1A = a0A + 16 * SB * 2;
    const uint32_t woff = (ncol * 32 + la7 + ((lane & 16) >> 1)) * CW + (lane & 8);
    const uint32_t p0A = smem_u32(sW0 + woff);
    const uint32_t q0A = smem_u32(sW1 + woff);
    uint32_t a0[2][4], a1[2][4], b0[2][4], b1[2][4];
    ldsm_x4(a0[0], a0A);
    ldsm_x4(b0[0], p0A);
    ldsm_x4(a1[0], a1A);
    ldsm_x4(b1[0], p0A + 16 * CW * 2);
#pragma unroll
    for (int ks = 0; ks < 128; ks += 16) {
        const int cur = (ks >> 4) & 1, nxt = cur ^ 1;
        if (ks < 112) {
            const int kn = ks + 16;
            // B base: chunk 0 for kn<64, chunk 1 (rebased) for kn>=64
            const uint32_t bb = (kn < 64) ? (p0A + kn * 2) : (q0A + (kn - 64) * 2);
            ldsm_x4(a0[nxt], a0A + kn * 2);
            ldsm_x4(b0[nxt], bb);
            ldsm_x4(a1[nxt], a1A + kn * 2);
            ldsm_x4(b1[nxt], bb + 16 * CW * 2);
        }
        mma4(acc + 0,  a0[cur], b0[cur][0], b0[cur][1]);
        mma4(acc + 4,  a0[cur], b0[cur][2], b0[cur][3]);
        mma4(acc + 8,  a0[cur], b1[cur][0], b1[cur][1]);
        mma4(acc + 12, a0[cur], b1[cur][2], b1[cur][3]);
        mma4(acc + 16, a1[cur], b0[cur][0], b0[cur][1]);
        mma4(acc + 20, a1[cur], b0[cur][2], b0[cur][3]);
        mma4(acc + 24, a1[cur], b1[cur][0], b1[cur][1]);
        mma4(acc + 28, a1[cur], b1[cur][2], b1[cur][3]);
    }
}

// paired warp GEMM half: two GEMMs sharing the SAME A fragments.
// A-fragments are software-pipelined; B loads stay adjacent to their MMAs.
__device__ __forceinline__ void gemm_pair(float* accP, float* accQ,
                                          const __nv_bfloat16* sA, int kbase,
                                          const __nv_bfloat16* sW0,
                                          const __nv_bfloat16* sW1,
                                          int lane, int mrow, int ncol) {
    const int la7 = lane & 7;
    const uint32_t a0A =
        smem_u32(sA + (mrow * 32 + la7 + (lane & 8)) * SB + kbase + ((lane & 16) ? 8 : 0));
    const uint32_t a1A = a0A + 16 * SB * 2;
    const uint32_t woff = (ncol * 32 + la7 + ((lane & 16) >> 1)) * CW + (lane & 8);
    const uint32_t p0A = smem_u32(sW0 + woff);
    const uint32_t p1A = p0A + 16 * CW * 2;
    const uint32_t q0A = smem_u32(sW1 + woff);
    const uint32_t q1A = q0A + 16 * CW * 2;
    uint32_t a0[2][4], a1[2][4];
    ldsm_x4(a0[0], a0A);
    ldsm_x4(a1[0], a1A);
#pragma unroll
    for (int ks = 0; ks < 64; ks += 16) {
        const int cur = (ks >> 4) & 1, nxt = cur ^ 1;
        uint32_t b0[4], b1[4];
        ldsm_x4(b0, p0A + ks * 2);
        ldsm_x4(b1, p1A + ks * 2);
        if (ks < 48) {
            ldsm_x4(a0[nxt], a0A + (ks + 16) * 2);
            ldsm_x4(a1[nxt], a1A + (ks + 16) * 2);
        }
        mma4(accP + 0,  a0[cur], b0[0], b0[1]);
        mma4(accP + 4,  a0[cur], b0[2], b0[3]);
        mma4(accP + 8,  a0[cur], b1[0], b1[1]);
        mma4(accP + 12, a0[cur], b1[2], b1[3]);
        mma4(accP + 16, a1[cur], b0[0], b0[1]);
        mma4(accP + 20, a1[cur], b0[2], b0[3]);
        mma4(accP + 24, a1[cur], b1[0], b1[1]);
        mma4(accP + 28, a1[cur], b1[2], b1[3]);
        ldsm_x4(b0, q0A + ks * 2);
        ldsm_x4(b1, q1A + ks * 2);
        mma4(accQ + 0,  a0[cur], b0[0], b0[1]);
        mma4(accQ + 4,  a0[cur], b0[2], b0[3]);
        mma4(accQ + 8,  a0[cur], b1[0], b1[1]);
        mma4(accQ + 12, a0[cur], b1[2], b1[3]);
        mma4(accQ + 16, a1[cur], b0[0], b0[1]);
        mma4(accQ + 20, a1[cur], b0[2], b0[3]);
        mma4(accQ + 24, a1[cur], b1[0], b1[1]);
        mma4(accQ + 28, a1[cur], b1[2], b1[3]);
    }
}
#define ACCI(t, ni) (((t) >> 1) * 16 + (ni) * 4 + ((t) & 1) * 2)

// epilogue via stmatrix: +bias (optional relu), store bf16 tile M32xN32
__device__ __forceinline__ void epi_sm(const float* acc, const float* __restrict__ bias,
                                       __nv_bfloat16* dst, int mrow, int ncol, int q2,
                                       int lane, bool relu) {
    const uint32_t abase = smem_u32(dst + (mrow * 32 + (lane & 7)) * SB
                                    + ncol * 32 + (lane >> 3) * 8);
#pragma unroll
    for (int t = 0; t < 4; t++) {
        uint32_t r[4];
#pragma unroll
        for (int m = 0; m < 4; m++) {
            int c = ncol * 32 + m * 8 + q2;
            const float* a = acc + ACCI(t, m);
            float v0 = a[0] + bias[c], v1 = a[1] + bias[c + 1];
            if (relu) { v0 = fmaxf(v0, 0.f); v1 = fmaxf(v1, 0.f); }
            r[m] = pack2(v0, v1);
        }
        stsm_x4(abase + (uint32_t)(t * 8 * SB * 2), r[0], r[1], r[2], r[3]);
    }
}

__global__ __launch_bounds__(THREADS, 2) void gat_fused_kernel(
    const float* __restrict__ tokens,
    const float* __restrict__ bq, const float* __restrict__ bk, const float* __restrict__ bv,
    const float* __restrict__ bo,
    const float* __restrict__ g1, const float* __restrict__ be1,
    const float* __restrict__ g2, const float* __restrict__ be2,
    const float* __restrict__ bf1, const float* __restrict__ bf2,
    float* __restrict__ out, int nBatch) {
    extern __shared__ char smem[];
    __nv_bfloat16* sXb = (__nv_bfloat16*)(smem + OFF_X);
    __nv_bfloat16* sQ = (__nv_bfloat16*)(smem + OFF_Q);
    __nv_bfloat16* sK = (__nv_bfloat16*)(smem + OFF_K);
    __nv_bfloat16* sV = (__nv_bfloat16*)(smem + OFF_V);
    __nv_bfloat16* sA = (__nv_bfloat16*)(smem + OFF_Q);     // in-place over sQ
    __nv_bfloat16* sB0 = (__nv_bfloat16*)(smem + OFF_B0);
    __nv_bfloat16* sB1 = (__nv_bfloat16*)(smem + OFF_B1);
    __nv_bfloat16* sH0 = (__nv_bfloat16*)(smem + OFF_Q);    // FF hidden 0-127
    __nv_bfloat16* sH1 = (__nv_bfloat16*)(smem + OFF_K);    // FF hidden 128-255
    __nv_bfloat16* sXD = (__nv_bfloat16*)(smem + OFF_V);    // x delta (over V)
    float2* sLN = (float2*)(smem + OFF_LN);

    const int tid = threadIdx.x;
    const int warp = tid >> 5;
    const int lane = tid & 31;
    const int mrow = warp >> 2;            // 0..1
    const int ncol = warp & 3;             // 0..3
    const int rbase = mrow * 32 + (lane >> 2);
    const int q2 = (lane & 3) * 2;

    const int item0 = blockIdx.x * BT;
    const int nItems = min(BT, nBatch - item0);
    const int nRows = nItems * J;

    // prologue: chunks c0 (Wq h0) -> B0, c2 (Wk h0) -> B1; tokens -> bf16
    pf_c(g_wt, sB0, tid);
    pf_c(g_wt + 2 * 8192, sB1, tid);
    {
        const float* tp = tokens + (size_t)item0 * (J * D);
        for (int i = tid; i < 2048; i += THREADS) {
            int r = i >> 5, c4 = (i & 31) * 4;
            float4 v = make_float4(0.f, 0.f, 0.f, 0.f);
            if (r < nRows) v = *(const float4*)(tp + r * D + c4);
            uint2 u;
            u.x = pack2(v.x, v.y);
            u.y = pack2(v.z, v.w);
            *(uint2*)(sXb + r * SB + c4) = u;
        }
    }

    float accq[32], acck[32];

    // ============ Phase P1: paired (Q, K) GEMMs sharing A fragments ============
#pragma unroll
    for (int i = 0; i < 32; i++) { accq[i] = 0.f; acck[i] = 0.f; }
    WAITG(0); __syncthreads();
    gemm_pair(accq, acck, sXb, 0, sB0, sB1, lane, mrow, ncol);
    __syncthreads();
    pf_c(g_wt + 1 * 8192, sB0, tid);   // Wq h1
    pf_c(g_wt + 3 * 8192, sB1, tid);   // Wk h1
    WAITG(0); __syncthreads();
    gemm_pair(accq, acck, sXb, 64, sB0, sB1, lane, mrow, ncol);
    __syncthreads();
    pf_c(g_wt + 4 * 8192, sB0, tid);   // Wv h0
    pf_c(g_wt + 5 * 8192, sB1, tid);   // Wv h1
    epi_sm(accq, bq, sQ, mrow, ncol, q2, lane, false);
    epi_sm(acck, bk, sK, mrow, ncol, q2, lane, false);
    // zero pad rows of sQ/sA (attention never writes them)
    for (int i = tid + nRows * 16; i < 64 * 16; i += THREADS) {
        int r = i >> 4, u = (i & 15) * 8;
        *(uint4*)(sA + r * SB + u) = make_uint4(0u, 0u, 0u, 0u);
    }

    // ============ Phase P2: V — fused full-K GEMM, defer Wo prefetch ============
#pragma unroll
    for (int i = 0; i < 32; i++) accq[i] = 0.f;
    WAITG(0); __syncthreads();         // Wv h0,h1 ready
    gemm_h2(accq, sXb, sB0, sB1, lane, mrow, ncol);
    __syncthreads();                   // all B0/B1 reads done
    pf_c(g_wt + 6 * 8192, sB0, tid);   // Wo h0 (covered by attention)
    pf_c(g_wt + 7 * 8192, sB1, tid);   // Wo h1
    epi_sm(accq, bv, sV, mrow, ncol, q2, lane, false);
    __syncthreads();                   // Q,K,V visible for attention

    // ====== Phase B: sparse masked attention — joint-major task order ======
    // task % 168: qi = rem >> 3 (0..20), hd = rem & 7 — concentrates the
    // 6-neighbor wrist rows into one warp instead of every warp.
    for (int task = tid; task < nItems * 168; task += THREADS) {
        const int it = task / 168;
        const int rem = task - it * 168;
        const int qi = rem >> 3;
        const int hd = rem & 7;
        const int rb = it * J;
        const int hb = hd * 16;

        float qv[16];
        ld16bf(sQ + (rb + qi) * SB + hb, qv);

        const int p = (qi - 1) & 3;
        const int cnt = (qi == 0) ? 6 : ((p == 3) ? 2 : 3);

        float av[16];
#pragma unroll
        for (int i = 0; i < 16; i++) av[i] = 0.f;
        float sum = 0.f;
#pragma unroll
        for (int n = 0; n < 6; n++) {
            if (n < cnt) {
                int kj;
                if (qi == 0) kj = (n == 0) ? 0 : 4 * n - 3;
                else kj = (n == 0) ? ((p == 0) ? 0 : qi - 1) : ((n == 1) ? qi : qi + 1);

                float kv[16];
                ld16bf(sK + (rb + kj) * SB + hb, kv);
                float d = 0.f;
#pragma unroll
                for (int i = 0; i < 16; i++) d = fmaf(qv[i], kv[i], d);
                float e = __expf(d * 0.25f);   // scores ~N(0,0.05): safe w/o max-sub
                sum += e;

                float vv[16];
                ld16bf(sV + (rb + kj) * SB + hb, vv);
#pragma unroll
                for (int i = 0; i < 16; i++) av[i] = fmaf(e, vv[i], av[i]);
            }
        }
        float inv = 1.f / sum;
        uint4 o0, o1;
        o0.x = pack2(av[0] * inv, av[1] * inv);   o0.y = pack2(av[2] * inv, av[3] * inv);
        o0.z = pack2(av[4] * inv, av[5] * inv);   o0.w = pack2(av[6] * inv, av[7] * inv);
        o1.x = pack2(av[8] * inv, av[9] * inv);   o1.y = pack2(av[10] * inv, av[11] * inv);
        o1.z = pack2(av[12] * inv, av[13] * inv); o1.w = pack2(av[14] * inv, av[15] * inv);
        __nv_bfloat16* arow = sA + (rb + qi) * SB + hb;     // in-place over own Q row
        *(uint4*)(arow) = o0;
        *(uint4*)(arow + 8) = o1;
    }

    // ===== Phase C: Wo — fused full-K GEMM, defer W1 prefetch; LN1 =====
    {
#pragma unroll
        for (int i = 0; i < 32; i++) accq[i] = 0.f;
        WAITG(0); __syncthreads();     // Wo chunks ready; attention writes visible
        gemm_h2(accq, sA, sB0, sB1, lane, mrow, ncol);
        __syncthreads();               // B0/B1 reads done
        pf_c(g_wt + 8 * 8192, sB0, tid);    // W1a h0 (covered by LN1 epilogue)
        pf_c(g_wt + 10 * 8192, sB1, tid);   // W1b h0

        float s[4], ss[4];
#pragma unroll
        for (int t = 0; t < 4; t++) {
            int R = rbase + t * 8;
            const bool okr = R < nRows;
            const float* tok = tokens + ((size_t)item0 * J + R) * D;
            s[t] = 0.f; ss[t] = 0.f;
#pragma unroll
            for (int ni = 0; ni < 4; ni++) {
                int c = ncol * 32 + ni * 8 + q2;
                float* a = accq + ACCI(t, ni);
                float2 bb = *(const float2*)(bo + c);
                float2 tk = okr ? *(const float2*)(tok + c) : make_float2(0.f, 0.f);
                float v0 = a[0] + bb.x + tk.x;
                float v1 = a[1] + bb.y + tk.y;
                a[0] = v0; a[1] = v1;
                s[t] += v0 + v1;
                ss[t] += v0 * v0 + v1 * v1;
            }
        }
#pragma unroll
        for (int t = 0; t < 4; t++) {
            s[t] += __shfl_xor_sync(0xffffffffu, s[t], 1);
            s[t] += __shfl_xor_sync(0xffffffffu, s[t], 2);
            ss[t] += __shfl_xor_sync(0xffffffffu, ss[t], 1);
            ss[t] += __shfl_xor_sync(0xffffffffu, ss[t], 2);
        }
        if ((lane & 3) == 0) {
#pragma unroll
            for (int t = 0; t < 4; t++)
                sLN[(rbase + t * 8) * 4 + ncol] = make_float2(s[t], ss[t]);
        }
        __syncthreads();
        const uint32_t abase = (mrow * 32 + (lane & 7)) * SB + ncol * 32 + (lane >> 3) * 8;
#pragma unroll
        for (int t = 0; t < 4; t++) {
            int R = rbase + t * 8;
            float2 p0 = sLN[R * 4 + 0], p1 = sLN[R * 4 + 1];
            float2 p2 = sLN[R * 4 + 2], p3 = sLN[R * 4 + 3];
            float mu = (p0.x + p1.x + p2.x + p3.x) * (1.f / 128.f);
            float iv = rsqrtf((p0.y + p1.y + p2.y + p3.y) * (1.f / 128.f) - mu * mu + 1e-5f);
            uint32_t rm[4], rd[4];
#pragma unroll
            for (int ni = 0; ni < 4; ni++) {
                int c = ncol * 32 + ni * 8 + q2;
                float* a = accq + ACCI(t, ni);
                float2 gg = *(const float2*)(g1 + c);
                float2 bb = *(const float2*)(be1 + c);
                float x0 = (a[0] - mu) * iv * gg.x + bb.x;
                float x1 = (a[1] - mu) * iv * gg.y + bb.y;
                __nv_bfloat162 m = __floats2bfloat162_rn(x0, x1);
                float2 f = __bfloat1622float2(m);
                rm[ni] = *(uint32_t*)&m;
                __nv_bfloat162 dl = __floats2bfloat162_rn(x0 - f.x, x1 - f.y);
                rd[ni] = *(uint32_t*)&dl;
            }
            uint32_t roff = abase + (uint32_t)(t * 8 * SB);
            stsm_x4(smem_u32(sXb + roff), rm[0], rm[1], rm[2], rm[3]);
            stsm_x4(smem_u32(sXD + roff), rd[0], rd[1], rd[2], rd[3]);
        }
    }

    // ============ Phase P5: paired (FF1a, FF1b) GEMMs sharing A fragments ============
#pragma unroll
    for (int i = 0; i < 32; i++) { accq[i] = 0.f; acck[i] = 0.f; }
    WAITG(0); __syncthreads();        // W1a/W1b h0 ready; sXb/sXD writes visible
    gemm_pair(accq, acck, sXb, 0, sB0, sB1, lane, mrow, ncol);
    __syncthreads();
    pf_c(g_wt + 9 * 8192, sB0, tid);    // W1a h1
    pf_c(g_wt + 11 * 8192, sB1, tid);   // W1b h1
    WAITG(0); __syncthreads();
    gemm_pair(accq, acck, sXb, 64, sB0, sB1, lane, mrow, ncol);
    __syncthreads();
    pf_c(g_wt + 12 * 8192, sB0, tid);   // W2a h0
    pf_c(g_wt + 13 * 8192, sB1, tid);   // W2a h1
    epi_sm(accq, bf1, sH0, mrow, ncol, q2, lane, true);
    epi_sm(acck, bf1 + 128, sH1, mrow, ncol, q2, lane, true);

    // ===== Phase E: FF2 = H0*W2a + H1*W2b + residual + LN2 =====
    {
#pragma unroll
        for (int i = 0; i < 32; i++) accq[i] = 0.f;
        WAITG(0); __syncthreads();     // W2a ready; H writes visible
        gemm_h(accq, sH0, 0, sB0, lane, mrow, ncol);
        __syncthreads();               // B0 reads done
        pf_c(g_wt + 14 * 8192, sB0, tid);   // W2b h0 (covered by next gemm)
        gemm_h(accq, sH0, 64, sB1, lane, mrow, ncol);
        __syncthreads();               // B1 reads done
        pf_c(g_wt + 15 * 8192, sB1, tid);   // W2b h1
        WAITG(1); __syncthreads();     // W2b h0 done
        gemm_h(accq, sH1, 0, sB0, lane, mrow, ncol);
        WAITG(0); __syncthreads();     // W2b h1 done
        gemm_h(accq, sH1, 64, sB1, lane, mrow, ncol);

        float s[4], ss[4];
#pragma unroll
        for (int t = 0; t < 4; t++) {
            int R = rbase + t * 8;
            s[t] = 0.f; ss[t] = 0.f;
#pragma unroll
            for (int ni = 0; ni < 4; ni++) {
                int c = ncol * 32 + ni * 8 + q2;
                float* a = accq + ACCI(t, ni);
                float2 bb = *(const float2*)(bf2 + c);
                float2 xb = __bfloat1622float2(*(__nv_bfloat162*)(sXb + R * SB + c));
                float2 xd = __bfloat1622float2(*(__nv_bfloat162*)(sXD + R * SB + c));
                float v0 = a[0] + bb.x + xb.x + xd.x;
                float v1 = a[1] + bb.y + xb.y + xd.y;
                a[0] = v0; a[1] = v1;
                s[t] += v0 + v1;
                ss[t] += v0 * v0 + v1 * v1;
            }
        }
#pragma unroll
        for (int t = 0; t < 4; t++) {
            s[t] += __shfl_xor_sync(0xffffffffu, s[t], 1);
            s[t] += __shfl_xor_sync(0xffffffffu, s[t], 2);
            ss[t] += __shfl_xor_sync(0xffffffffu, ss[t], 1);
            ss[t] += __shfl_xor_sync(0xffffffffu, ss[t], 2);
        }
        if ((lane & 3) == 0) {
#pragma unroll
            for (int t = 0; t < 4; t++)
                sLN[(rbase + t * 8) * 4 + ncol] = make_float2(s[t], ss[t]);
        }
        __syncthreads();
#pragma unroll
        for (int t = 0; t < 4; t++) {
            int R = rbase + t * 8;
            float2 p0 = sLN[R * 4 + 0], p1 = sLN[R * 4 + 1];
            float2 p2 = sLN[R * 4 + 2], p3 = sLN[R * 4 + 3];
            float mu = (p0.x + p1.x + p2.x + p3.x) * (1.f / 128.f);
            float iv = rsqrtf((p0.y + p1.y + p2.y + p3.y) * (1.f / 128.f) - mu * mu + 1e-5f);
            if (R < nRows) {
                float* orow = out + ((size_t)item0 * J + R) * D;
#pragma unroll
                for (int ni = 0; ni < 4; ni++) {
                    int c = ncol * 32 + ni * 8 + q2;
                    const float* a = accq + ACCI(t, ni);
                    float2 gg = *(const float2*)(g2 + c);
                    float2 bb = *(const float2*)(be2 + c);
                    *(float2*)(orow + c) = make_float2((a[0] - mu) * iv * gg.x + bb.x,
                                                       (a[1] - mu) * iv * gg.y + bb.y);
                }
            }
        }
    }
}

extern "C" void kernel_launch(void* const* d_in, const int* in_sizes, int n_in,
                              void* d_out, int out_size) {
    const float* tokens = (const float*)d_in[0];
    const float* Wq = (const float*)d_in[1];  const float* bq = (const float*)d_in[2];
    const float* Wk = (const float*)d_in[3];  const float* bk = (const float*)d_in[4];
    const float* Wv = (const float*)d_in[5];  const float* bv = (const float*)d_in[6];
    const float* Wo = (const float*)d_in[7];  const float* bo = (const float*)d_in[8];
    const float* g1 = (const float*)d_in[9];  const float* be1 = (const float*)d_in[10];
    const float* g2 = (const float*)d_in[11]; const float* be2 = (const float*)d_in[12];
    const float* W1 = (const float*)d_in[13]; const float* bf1 = (const float*)d_in[14];
    const float* W2 = (const float*)d_in[15]; const float* bf2 = (const float*)d_in[16];
    float* out = (float*)d_out;

    int nBatch = in_sizes[0] / (J * D);
    int nCTA = (nBatch + BT - 1) / BT;

    cudaFuncSetAttribute(gat_fused_kernel, cudaFuncAttributeMaxDynamicSharedMemorySize,
                         SMEM_TOTAL);

    prep_weights<<<512, 256>>>(Wq, Wk, Wv, Wo, W1, W2);
    gat_fused_kernel<<<nCTA, THREADS, SMEM_TOTAL>>>(tokens, bq, bk, bv, bo, g1, be1,
                                                    g2, be2, bf1, bf2, out, nBatch);
}

// round 17
// speedup vs baseline: 1.0156x; 1.0009x over previous
#include <cuda_runtime.h>
#include <cuda_bf16.h>
#include <cstdint>

#define J 21
#define D 128
#define BT 3                  // batch items per CTA -> 63 rows, pad to 64
#define THREADS 256
#define SB 136                // bf16 stride of activation tiles (272B rows)
#define CW 72                 // bf16 stride of weight chunk rows (144B rows)

#define OFF_X  0              // tokens -> x bf16 (GEMM A operand)        17408
#define OFF_Q  17408          // sQ -> sA (in place) -> sH0               17408
#define OFF_K  34816          // sK -> sH1                                17408
#define OFF_V  52224          // sV -> x delta (bf16)                     17408
#define OFF_B0 69632          // weight chunk buffer 0 (128x72x2)         18432
#define OFF_B1 88064          // weight chunk buffer 1                    18432
#define OFF_LN 106496         // 64 rows x 4 float2                        2048
#define SMEM_TOTAL 108544

// 16 weight chunks, each [128 n][64 k] bf16 packed (n*64+kk), 8192 elems.
// chunk c: tile t=c>>1 (0..7 = WqT,WkT,WvT,WoT,W1aT,W1bT,W2aT,W2bT), k-half h=c&1.
__device__ __align__(16) __nv_bfloat16 g_wt[131072];

__global__ void prep_weights(const float* __restrict__ Wq, const float* __restrict__ Wk,
                             const float* __restrict__ Wv, const float* __restrict__ Wo,
                             const float* __restrict__ W1, const float* __restrict__ W2) {
    int i = blockIdx.x * blockDim.x + threadIdx.x;
    if (i >= 131072) return;
    int c = i >> 13, j = i & 8191;
    int n = j >> 6, kk = j & 63;
    int t = c >> 1, k = (c & 1) * 64 + kk;
    float v;
    if (t < 4) {
        const float* W = (t == 0) ? Wq : (t == 1) ? Wk : (t == 2) ? Wv : Wo;
        v = W[k * 128 + n];
    } else if (t == 4) v = W1[k * 256 + n];
    else if (t == 5) v = W1[k * 256 + 128 + n];
    else if (t == 6) v = W2[k * 128 + n];
    else v = W2[(128 + k) * 128 + n];
    g_wt[i] = __float2bfloat16(v);
}

__device__ __forceinline__ uint32_t smem_u32(const void* p) {
    return (uint32_t)__cvta_generic_to_shared(p);
}

__device__ __forceinline__ void ldsm_x4(uint32_t* r, uint32_t addr) {
    asm volatile("ldmatrix.sync.aligned.m8n8.x4.shared.b16 {%0,%1,%2,%3}, [%4];\n"
                 : "=r"(r[0]), "=r"(r[1]), "=r"(r[2]), "=r"(r[3]) : "r"(addr));
}

__device__ __forceinline__ void stsm_x4(uint32_t addr, uint32_t r0, uint32_t r1,
                                        uint32_t r2, uint32_t r3) {
    asm volatile("stmatrix.sync.aligned.m8n8.x4.shared.b16 [%0], {%1,%2,%3,%4};\n"
                 :: "r"(addr), "r"(r0), "r"(r1), "r"(r2), "r"(r3) : "memory");
}

__device__ __forceinline__ void mma4(float* c, const uint32_t* a, uint32_t b0, uint32_t b1) {
    asm volatile(
        "mma.sync.aligned.m16n8k16.row.col.f32.bf16.bf16.f32 "
        "{%0,%1,%2,%3}, {%4,%5,%6,%7}, {%8,%9}, {%0,%1,%2,%3};\n"
        : "+f"(c[0]), "+f"(c[1]), "+f"(c[2]), "+f"(c[3])
        : "r"(a[0]), "r"(a[1]), "r"(a[2]), "r"(a[3]), "r"(b0), "r"(b1));
}

__device__ __forceinline__ uint32_t pack2(float x, float y) {
    __nv_bfloat162 t = __floats2bfloat162_rn(x, y);
    return *reinterpret_cast<uint32_t*>(&t);
}

// streaming 64-bit store (evict-first: out is write-once, never re-read)
__device__ __forceinline__ void stg_cs8(float* p, float x, float y) {
    float2 v = make_float2(x, y);
    asm volatile("st.global.cs.v2.f32 [%0], {%1, %2};\n" :: "l"(p), "f"(v.x), "f"(v.y)
                 : "memory");
}

// load 16 consecutive bf16 (16B-aligned) -> 16 floats
__device__ __forceinline__ void ld16bf(const __nv_bfloat16* p, float* f) {
    uint4 u0 = *(const uint4*)(p);
    uint4 u1 = *(const uint4*)(p + 8);
    uint32_t w[8] = {u0.x, u0.y, u0.z, u0.w, u1.x, u1.y, u1.z, u1.w};
#pragma unroll
    for (int i = 0; i < 8; i++) {
        float2 g = __bfloat1622float2(*(const __nv_bfloat162*)&w[i]);
        f[2 * i] = g.x;
        f[2 * i + 1] = g.y;
    }
}

// async prefetch of one [128 n][64 k] chunk into sW (stride CW), no wait
__device__ __forceinline__ void pf_c(const __nv_bfloat16* g, __nv_bfloat16* sW, int tid) {
#pragma unroll
    for (int i = tid; i < 1024; i += THREADS) {
        int n = i >> 3, u = (i & 7) * 8;
        asm volatile("cp.async.cg.shared.global [%0], [%1], 16;\n"
                     :: "r"(smem_u32(sW + n * CW + u)), "l"(g + n * 64 + u));
    }
    asm volatile("cp.async.commit_group;\n" ::: "memory");
}
#define WAITG(N) asm volatile("cp.async.wait_group %0;\n" :: "n"(N) : "memory")

// warp GEMM half with software-pipelined fragments:
// acc[M32 x N32] += A[M32 x k64 @ kbase] @ chunk^T
__device__ __forceinline__ void gemm_h(float* acc, const __nv_bfloat16* sA, int kbase,
                                       const __nv_bfloat16* sW,
                                       int lane, int mrow, int ncol) {
    const int la7 = lane & 7;
    const uint32_t a0A =
        smem_u32(sA + (mrow * 32 + la7 + (lane & 8)) * SB + kbase + ((lane & 16) ? 8 : 0));
    const uint32_t a1A = a0A + 16 * SB * 2;
    const uint32_t b0A =
        smem_u32(sW + (ncol * 32 + la7 + ((lane & 16) >> 1)) * CW + (lane & 8));
    const uint32_t b1A = b0A + 16 * CW * 2;
    uint32_t a0[2][4], a1[2][4], b0[2][4], b1[2][4];
    ldsm_x4(a0[0], a0A);
    ldsm_x4(b0[0], b0A);
    ldsm_x4(a1[0], a1A);
    ldsm_x4(b1[0], b1A);
#pragma unroll
    for (int ks = 0; ks < 64; ks += 16) {
        const int cur = (ks >> 4) & 1, nxt = cur ^ 1;
        if (ks < 48) {
            ldsm_x4(a0[nxt], a0A + (ks + 16) * 2);
            ldsm_x4(b0[nxt], b0A + (ks + 16) * 2);
            ldsm_x4(a1[nxt], a1A + (ks + 16) * 2);
            ldsm_x4(b1[nxt], b1A + (ks + 16) * 2);
        }
        mma4(acc + 0,  a0[cur], b0[cur][0], b0[cur][1]);
        mma4(acc + 4,  a0[cur], b0[cur][2], b0[cur][3]);
        mma4(acc + 8,  a0[cur], b1[cur][0], b1[cur][1]);
        mma4(acc + 12, a0[cur], b1[cur][2], b1[cur][3]);
        mma4(acc + 16, a1[cur], b0[cur][0], b0[cur][1]);
        mma4(acc + 20, a1[cur], b0[cur][2], b0[cur][3]);
        mma4(acc + 24, a1[cur], b1[cur][0], b1[cur][1]);
        mma4(acc + 28, a1[cur], b1[cur][2], b1[cur][3]);
    }
}

// full-K warp GEMM: acc[M32 x N32] += A[M32 x K128] with k0-63 from chunk sW0
// and k64-127 from chunk sW1, one continuous software pipeline (no mid drain).
__device__ __forceinline__ void gemm_h2(float* acc, const __nv_bfloat16* sA,
                                        const __nv_bfloat16* sW0,
                                        const __nv_bfloat16* sW1,
                                        int lane, int mrow, int ncol) {
    const int la7 = lane & 7;
    const uint32_t a0A =
        smem_u32(sA + (mrow * 32 + la7 + (lane & 8)) * SB + ((lane & 16) ? 8 : 0));
    const uint32_t a1A = a0A + 16 * SB * 2;
    const uint32_t woff = (ncol * 32 + la7 + ((lane & 16) >> 1)) * CW + (lane & 8);
    const uint32_t p0A = smem_u32(sW0 + woff);
    const uint32_t q0A = smem_u32(sW1 + woff);
    uint32_t a0[2][4], a1[2][4], b0[2][4], b1[2][4];
    ldsm_x4(a0[0], a0A);
    ldsm_x4(b0[0], p0A);
    ldsm_x4(a1[0], a1A);
    ldsm_x4(b1[0], p0A + 16 * CW * 2);
#pragma unroll
    for (int ks = 0; ks < 128; ks += 16) {
        const int cur = (ks >> 4) & 1, nxt = cur ^ 1;
        if (ks < 112) {
            const int kn = ks + 16;
            const uint32_t bb = (kn < 64) ? (p0A + kn * 2) : (q0A + (kn - 64) * 2);
            ldsm_x4(a0[nxt], a0A + kn * 2);
            ldsm_x4(b0[nxt], bb);
            ldsm_x4(a1[nxt], a1A + kn * 2);
            ldsm_x4(b1[nxt], bb + 16 * CW * 2);
        }
        mma4(acc + 0,  a0[cur], b0[cur][0], b0[cur][1]);
        mma4(acc + 4,  a0[cur], b0[cur][2], b0[cur][3]);
        mma4(acc + 8,  a0[cur], b1[cur][0], b1[cur][1]);
        mma4(acc + 12, a0[cur], b1[cur][2], b1[cur][3]);
        mma4(acc + 16, a1[cur], b0[cur][0], b0[cur][1]);
        mma4(acc + 20, a1[cur], b0[cur][2], b0[cur][3]);
        mma4(acc + 24, a1[cur], b1[cur][0], b1[cur][1]);
        mma4(acc + 28, a1[cur], b1[cur][2], b1[cur][3]);
    }
}

// paired warp GEMM half: two GEMMs sharing the SAME A fragments.
__device__ __forceinline__ void gemm_pair(float* accP, float* accQ,
                                          const __nv_bfloat16* sA, int kbase,
                                          const __nv_bfloat16* sW0,
                                          const __nv_bfloat16* sW1,
                                          int lane, int mrow, int ncol) {
    const int la7 = lane & 7;
    const uint32_t a0A =
        smem_u32(sA + (mrow * 32 + la7 + (lane & 8)) * SB + kbase + ((lane & 16) ? 8 : 0));
    const uint32_t a1A = a0A + 16 * SB * 2;
    const uint32_t woff = (ncol * 32 + la7 + ((lane & 16) >> 1)) * CW + (lane & 8);
    const uint32_t p0A = smem_u32(sW0 + woff);
    const uint32_t p1A = p0A + 16 * CW * 2;
    const uint32_t q0A = smem_u32(sW1 + woff);
    const uint32_t q1A = q0A + 16 * CW * 2;
    uint32_t a0[2][4], a1[2][4];
    ldsm_x4(a0[0], a0A);
    ldsm_x4(a1[0], a1A);
#pragma unroll
    for (int ks = 0; ks < 64; ks += 16) {
        const int cur = (ks >> 4) & 1, nxt = cur ^ 1;
        uint32_t b0[4], b1[4];
        ldsm_x4(b0, p0A + ks * 2);
        ldsm_x4(b1, p1A + ks * 2);
        if (ks < 48) {
            ldsm_x4(a0[nxt], a0A + (ks + 16) * 2);
            ldsm_x4(a1[nxt], a1A + (ks + 16) * 2);
        }
        mma4(accP + 0,  a0[cur], b0[0], b0[1]);
        mma4(accP + 4,  a0[cur], b0[2], b0[3]);
        mma4(accP + 8,  a0[cur], b1[0], b1[1]);
        mma4(accP + 12, a0[cur], b1[2], b1[3]);
        mma4(accP + 16, a1[cur], b0[0], b0[1]);
        mma4(accP + 20, a1[cur], b0[2], b0[3]);
        mma4(accP + 24, a1[cur], b1[0], b1[1]);
        mma4(accP + 28, a1[cur], b1[2], b1[3]);
        ldsm_x4(b0, q0A + ks * 2);
        ldsm_x4(b1, q1A + ks * 2);
        mma4(accQ + 0,  a0[cur], b0[0], b0[1]);
        mma4(accQ + 4,  a0[cur], b0[2], b0[3]);
        mma4(accQ + 8,  a0[cur], b1[0], b1[1]);
        mma4(accQ + 12, a0[cur], b1[2], b1[3]);
        mma4(accQ + 16, a1[cur], b0[0], b0[1]);
        mma4(accQ + 20, a1[cur], b0[2], b0[3]);
        mma4(accQ + 24, a1[cur], b1[0], b1[1]);
        mma4(accQ + 28, a1[cur], b1[2], b1[3]);
    }
}
#define ACCI(t, ni) (((t) >> 1) * 16 + (ni) * 4 + ((t) & 1) * 2)

// epilogue via stmatrix: +bias (optional relu), store bf16 tile M32xN32
__device__ __forceinline__ void epi_sm(const float* acc, const float* __restrict__ bias,
                                       __nv_bfloat16* dst, int mrow, int ncol, int q2,
                                       int lane, bool relu) {
    const uint32_t abase = smem_u32(dst + (mrow * 32 + (lane & 7)) * SB
                                    + ncol * 32 + (lane >> 3) * 8);
#pragma unroll
    for (int t = 0; t < 4; t++) {
        uint32_t r[4];
#pragma unroll
        for (int m = 0; m < 4; m++) {
            int c = ncol * 32 + m * 8 + q2;
            const float* a = acc + ACCI(t, m);
            float v0 = a[0] + bias[c], v1 = a[1] + bias[c + 1];
            if (relu) { v0 = fmaxf(v0, 0.f); v1 = fmaxf(v1, 0.f); }
            r[m] = pack2(v0, v1);
        }
        stsm_x4(abase + (uint32_t)(t * 8 * SB * 2), r[0], r[1], r[2], r[3]);
    }
}

__global__ __launch_bounds__(THREADS, 2) void gat_fused_kernel(
    const float* __restrict__ tokens,
    const float* __restrict__ bq, const float* __restrict__ bk, const float* __restrict__ bv,
    const float* __restrict__ bo,
    const float* __restrict__ g1, const float* __restrict__ be1,
    const float* __restrict__ g2, const float* __restrict__ be2,
    const float* __restrict__ bf1, const float* __restrict__ bf2,
    float* __restrict__ out, int nBatch) {
    extern __shared__ char smem[];
    __nv_bfloat16* sXb = (__nv_bfloat16*)(smem + OFF_X);
    __nv_bfloat16* sQ = (__nv_bfloat16*)(smem + OFF_Q);
    __nv_bfloat16* sK = (__nv_bfloat16*)(smem + OFF_K);
    __nv_bfloat16* sV = (__nv_bfloat16*)(smem + OFF_V);
    __nv_bfloat16* sA = (__nv_bfloat16*)(smem + OFF_Q);     // in-place over sQ
    __nv_bfloat16* sB0 = (__nv_bfloat16*)(smem + OFF_B0);
    __nv_bfloat16* sB1 = (__nv_bfloat16*)(smem + OFF_B1);
    __nv_bfloat16* sH0 = (__nv_bfloat16*)(smem + OFF_Q);    // FF hidden 0-127
    __nv_bfloat16* sH1 = (__nv_bfloat16*)(smem + OFF_K);    // FF hidden 128-255
    __nv_bfloat16* sXD = (__nv_bfloat16*)(smem + OFF_V);    // x delta (over V)
    float2* sLN = (float2*)(smem + OFF_LN);

    const int tid = threadIdx.x;
    const int warp = tid >> 5;
    const int lane = tid & 31;
    const int mrow = warp >> 2;            // 0..1
    const int ncol = warp & 3;             // 0..3
    const int rbase = mrow * 32 + (lane >> 2);
    const int q2 = (lane & 3) * 2;

    const int item0 = blockIdx.x * BT;
    const int nItems = min(BT, nBatch - item0);
    const int nRows = nItems * J;

    // prologue: chunks c0 (Wq h0) -> B0, c2 (Wk h0) -> B1; tokens -> bf16
    pf_c(g_wt, sB0, tid);
    pf_c(g_wt + 2 * 8192, sB1, tid);
    {
        const float* tp = tokens + (size_t)item0 * (J * D);
        for (int i = tid; i < 2048; i += THREADS) {
            int r = i >> 5, c4 = (i & 31) * 4;
            float4 v = make_float4(0.f, 0.f, 0.f, 0.f);
            if (r < nRows) v = *(const float4*)(tp + r * D + c4);
            uint2 u;
            u.x = pack2(v.x, v.y);
            u.y = pack2(v.z, v.w);
            *(uint2*)(sXb + r * SB + c4) = u;
        }
    }

    float accq[32], acck[32];

    // ============ Phase P1: paired (Q, K) GEMMs sharing A fragments ============
#pragma unroll
    for (int i = 0; i < 32; i++) { accq[i] = 0.f; acck[i] = 0.f; }
    WAITG(0); __syncthreads();
    gemm_pair(accq, acck, sXb, 0, sB0, sB1, lane, mrow, ncol);
    __syncthreads();
    pf_c(g_wt + 1 * 8192, sB0, tid);   // Wq h1
    pf_c(g_wt + 3 * 8192, sB1, tid);   // Wk h1
    WAITG(0); __syncthreads();
    gemm_pair(accq, acck, sXb, 64, sB0, sB1, lane, mrow, ncol);
    __syncthreads();
    pf_c(g_wt + 4 * 8192, sB0, tid);   // Wv h0
    pf_c(g_wt + 5 * 8192, sB1, tid);   // Wv h1
    epi_sm(accq, bq, sQ, mrow, ncol, q2, lane, false);
    epi_sm(acck, bk, sK, mrow, ncol, q2, lane, false);
    // zero pad rows of sQ/sA (attention never writes them)
    for (int i = tid + nRows * 16; i < 64 * 16; i += THREADS) {
        int r = i >> 4, u = (i & 15) * 8;
        *(uint4*)(sA + r * SB + u) = make_uint4(0u, 0u, 0u, 0u);
    }

    // ============ Phase P2: V — fused full-K GEMM, defer Wo prefetch ============
#pragma unroll
    for (int i = 0; i < 32; i++) accq[i] = 0.f;
    WAITG(0); __syncthreads();         // Wv h0,h1 ready
    gemm_h2(accq, sXb, sB0, sB1, lane, mrow, ncol);
    __syncthreads();                   // all B0/B1 reads done
    pf_c(g_wt + 6 * 8192, sB0, tid);   // Wo h0 (covered by attention)
    pf_c(g_wt + 7 * 8192, sB1, tid);   // Wo h1
    epi_sm(accq, bv, sV, mrow, ncol, q2, lane, false);
    __syncthreads();                   // Q,K,V visible for attention

    // ====== Phase B: sparse masked attention — joint-major, div-free loop ======
    {
        int it = tid / 168;
        int rem = tid - it * 168;
        const int total = nItems * 168;
        for (int task = tid; task < total; task += THREADS) {
            const int qi = rem >> 3;
            const int hd = rem & 7;
            const int rb = it * J;
            const int hb = hd * 16;

            float qv[16];
            ld16bf(sQ + (rb + qi) * SB + hb, qv);

            const int p = (qi - 1) & 3;
            const int cnt = (qi == 0) ? 6 : ((p == 3) ? 2 : 3);

            float av[16];
#pragma unroll
            for (int i = 0; i < 16; i++) av[i] = 0.f;
            float sum = 0.f;
#pragma unroll
            for (int n = 0; n < 6; n++) {
                if (n < cnt) {
                    int kj;
                    if (qi == 0) kj = (n == 0) ? 0 : 4 * n - 3;
                    else kj = (n == 0) ? ((p == 0) ? 0 : qi - 1) : ((n == 1) ? qi : qi + 1);

                    float kv[16];
                    ld16bf(sK + (rb + kj) * SB + hb, kv);
                    float d = 0.f;
#pragma unroll
                    for (int i = 0; i < 16; i++) d = fmaf(qv[i], kv[i], d);
                    float e = __expf(d * 0.25f);   // scores ~N(0,0.05): safe w/o max-sub
                    sum += e;

                    float vv[16];
                    ld16bf(sV + (rb + kj) * SB + hb, vv);
#pragma unroll
                    for (int i = 0; i < 16; i++) av[i] = fmaf(e, vv[i], av[i]);
                }
            }
            float inv = 1.f / sum;
            uint4 o0, o1;
            o0.x = pack2(av[0] * inv, av[1] * inv);   o0.y = pack2(av[2] * inv, av[3] * inv);
            o0.z = pack2(av[4] * inv, av[5] * inv);   o0.w = pack2(av[6] * inv, av[7] * inv);
            o1.x = pack2(av[8] * inv, av[9] * inv);   o1.y = pack2(av[10] * inv, av[11] * inv);
            o1.z = pack2(av[12] * inv, av[13] * inv); o1.w = pack2(av[14] * inv, av[15] * inv);
            __nv_bfloat16* arow = sA + (rb + qi) * SB + hb;   // in-place over own Q row
            *(uint4*)(arow) = o0;
            *(uint4*)(arow + 8) = o1;

            // incremental (it, rem) advance: rem += 256 - k*168 with carry
            rem += THREADS - 168;
            it += 1;
            if (rem >= 168) { rem -= 168; it += 1; }
        }
    }

    // ===== Phase C: Wo — fused full-K GEMM, defer W1 prefetch; LN1 =====
    {
#pragma unroll
        for (int i = 0; i < 32; i++) accq[i] = 0.f;
        WAITG(0); __syncthreads();     // Wo chunks ready; attention writes visible
        gemm_h2(accq, sA, sB0, sB1, lane, mrow, ncol);
        __syncthreads();               // B0/B1 reads done
        pf_c(g_wt + 8 * 8192, sB0, tid);    // W1a h0 (covered by LN1 epilogue)
        pf_c(g_wt + 10 * 8192, sB1, tid);   // W1b h0

        float s[4], ss[4];
#pragma unroll
        for (int t = 0; t < 4; t++) {
            int R = rbase + t * 8;
            const bool okr = R < nRows;
            const float* tok = tokens + ((size_t)item0 * J + R) * D;
            s[t] = 0.f; ss[t] = 0.f;
#pragma unroll
            for (int ni = 0; ni < 4; ni++) {
                int c = ncol * 32 + ni * 8 + q2;
                float* a = accq + ACCI(t, ni);
                float2 bb = *(const float2*)(bo + c);
                float2 tk = okr ? *(const float2*)(tok + c) : make_float2(0.f, 0.f);
                float v0 = a[0] + bb.x + tk.x;
                float v1 = a[1] + bb.y + tk.y;
                a[0] = v0; a[1] = v1;
                s[t] += v0 + v1;
                ss[t] += v0 * v0 + v1 * v1;
            }
        }
#pragma unroll
        for (int t = 0; t < 4; t++) {
            s[t] += __shfl_xor_sync(0xffffffffu, s[t], 1);
            s[t] += __shfl_xor_sync(0xffffffffu, s[t], 2);
            ss[t] += __shfl_xor_sync(0xffffffffu, ss[t], 1);
            ss[t] += __shfl_xor_sync(0xffffffffu, ss[t], 2);
        }
        if ((lane & 3) == 0) {
#pragma unroll
            for (int t = 0; t < 4; t++)
                sLN[(rbase + t * 8) * 4 + ncol] = make_float2(s[t], ss[t]);
        }
        __syncthreads();
        const uint32_t abase = (mrow * 32 + (lane & 7)) * SB + ncol * 32 + (lane >> 3) * 8;
#pragma unroll
        for (int t = 0; t < 4; t++) {
            int R = rbase + t * 8;
            float2 p0 = sLN[R * 4 + 0], p1 = sLN[R * 4 + 1];
            float2 p2 = sLN[R * 4 + 2], p3 = sLN[R * 4 + 3];
            float mu = (p0.x + p1.x + p2.x + p3.x) * (1.f / 128.f);
            float iv = rsqrtf((p0.y + p1.y + p2.y + p3.y) * (1.f / 128.f) - mu * mu + 1e-5f);
            uint32_t rm[4], rd[4];
#pragma unroll
            for (int ni = 0; ni < 4; ni++) {
                int c = ncol * 32 + ni * 8 + q2;
                float* a = accq + ACCI(t, ni);
                float2 gg = *(const float2*)(g1 + c);
                float2 bb = *(const float2*)(be1 + c);
                float x0 = (a[0] - mu) * iv * gg.x + bb.x;
                float x1 = (a[1] - mu) * iv * gg.y + bb.y;
                __nv_bfloat162 m = __floats2bfloat162_rn(x0, x1);
                float2 f = __bfloat1622float2(m);
                rm[ni] = *(uint32_t*)&m;
                __nv_bfloat162 dl = __floats2bfloat162_rn(x0 - f.x, x1 - f.y);
                rd[ni] = *(uint32_t*)&dl;
            }
            uint32_t roff = abase + (uint32_t)(t * 8 * SB);
            stsm_x4(smem_u32(sXb + roff), rm[0], rm[1], rm[2], rm[3]);
            stsm_x4(smem_u32(sXD + roff), rd[0], rd[1], rd[2], rd[3]);
        }
    }

    // ============ Phase P5: paired (FF1a, FF1b) GEMMs sharing A fragments ============
#pragma unroll
    for (int i = 0; i < 32; i++) { accq[i] = 0.f; acck[i] = 0.f; }
    WAITG(0); __syncthreads();        // W1a/W1b h0 ready; sXb/sXD writes visible
    gemm_pair(accq, acck, sXb, 0, sB0, sB1, lane, mrow, ncol);
    __syncthreads();
    pf_c(g_wt + 9 * 8192, sB0, tid);    // W1a h1
    pf_c(g_wt + 11 * 8192, sB1, tid);   // W1b h1
    WAITG(0); __syncthreads();
    gemm_pair(accq, acck, sXb, 64, sB0, sB1, lane, mrow, ncol);
    __syncthreads();
    pf_c(g_wt + 12 * 8192, sB0, tid);   // W2a h0
    pf_c(g_wt + 13 * 8192, sB1, tid);   // W2a h1
    epi_sm(accq, bf1, sH0, mrow, ncol, q2, lane, true);
    epi_sm(acck, bf1 + 128, sH1, mrow, ncol, q2, lane, true);

    // ===== Phase E: FF2 = H0*W2a + H1*W2b + residual + LN2 =====
    {
#pragma unroll
        for (int i = 0; i < 32; i++) accq[i] = 0.f;
        WAITG(0); __syncthreads();     // W2a ready; H writes visible
        gemm_h(accq, sH0, 0, sB0, lane, mrow, ncol);
        __syncthreads();               // B0 reads done
        pf_c(g_wt + 14 * 8192, sB0, tid);   // W2b h0 (covered by next gemm)
        gemm_h(accq, sH0, 64, sB1, lane, mrow, ncol);
        __syncthreads();               // B1 reads done
        pf_c(g_wt + 15 * 8192, sB1, tid);   // W2b h1
        WAITG(1); __syncthreads();     // W2b h0 done
        gemm_h(accq, sH1, 0, sB0, lane, mrow, ncol);
        WAITG(0); __syncthreads();     // W2b h1 done
        gemm_h(accq, sH1, 64, sB1, lane, mrow, ncol);

        float s[4], ss[4];
#pragma unroll
        for (int t = 0; t < 4; t++) {
            int R = rbase + t * 8;
            s[t] = 0.f; ss[t] = 0.f;
#pragma unroll
            for (int ni = 0; ni < 4; ni++) {
                int c = ncol * 32 + ni * 8 + q2;
                float* a = accq + ACCI(t, ni);
                float2 bb = *(const float2*)(bf2 + c);
                float2 xb = __bfloat1622float2(*(__nv_bfloat162*)(sXb + R * SB + c));
                float2 xd = __bfloat1622float2(*(__nv_bfloat162*)(sXD + R * SB + c));
                float v0 = a[0] + bb.x + xb.x + xd.x;
                float v1 = a[1] + bb.y + xb.y + xd.y;
                a[0] = v0; a[1] = v1;
                s[t] += v0 + v1;
                ss[t] += v0 * v0 + v1 * v1;
            }
        }
#pragma unroll
        for (int t = 0; t < 4; t++) {
            s[t] += __shfl_xor_sync(0xffffffffu, s[t], 1);
            s[t] += __shfl_xor_sync(0xffffffffu, s[t], 2);
            ss[t] += __shfl_xor_sync(0xffffffffu, ss[t], 1);
            ss[t] += __shfl_xor_sync(0xffffffffu, ss[t], 2);
        }
        if ((lane & 3) == 0) {
#pragma unroll
            for (int t = 0; t < 4; t++)
                sLN[(rbase + t * 8) * 4 + ncol] = make_float2(s[t], ss[t]);
        }
        __syncthreads();
#pragma unroll
        for (int t = 0; t < 4; t++) {
            int R = rbase + t * 8;
            float2 p0 = sLN[R * 4 + 0], p1 = sLN[R * 4 + 1];
            float2 p2 = sLN[R * 4 + 2], p3 = sLN[R * 4 + 3];
            float mu = (p0.x + p1.x + p2.x + p3.x) * (1.f / 128.f);
            float iv = rsqrtf((p0.y + p1.y + p2.y + p3.y) * (1.f / 128.f) - mu * mu + 1e-5f);
            if (R < nRows) {
                float* orow = out + ((size_t)item0 * J + R) * D;
#pragma unroll
                for (int ni = 0; ni < 4; ni++) {
                    int c = ncol * 32 + ni * 8 + q2;
                    const float* a = accq + ACCI(t, ni);
                    float2 gg = *(const float2*)(g2 + c);
                    float2 bb = *(const float2*)(be2 + c);
                    stg_cs8(orow + c, (a[0] - mu) * iv * gg.x + bb.x,
                            (a[1] - mu) * iv * gg.y + bb.y);
                }
            }
        }
    }
}

extern "C" void kernel_launch(void* const* d_in, const int* in_sizes, int n_in,
                              void* d_out, int out_size) {
    const float* tokens = (const float*)d_in[0];
    const float* Wq = (const float*)d_in[1];  const float* bq = (const float*)d_in[2];
    const float* Wk = (const float*)d_in[3];  const float* bk = (const float*)d_in[4];
    const float* Wv = (const float*)d_in[5];  const float* bv = (const float*)d_in[6];
    const float* Wo = (const float*)d_in[7];  const float* bo = (const float*)d_in[8];
    const float* g1 = (const float*)d_in[9];  const float* be1 = (const float*)d_in[10];
    const float* g2 = (const float*)d_in[11]; const float* be2 = (const float*)d_in[12];
    const float* W1 = (const float*)d_in[13]; const float* bf1 = (const float*)d_in[14];
    const float* W2 = (const float*)d_in[15]; const float* bf2 = (const float*)d_in[16];
    float* out = (float*)d_out;

    int nBatch = in_sizes[0] / (J * D);
    int nCTA = (nBatch + BT - 1) / BT;

    cudaFuncSetAttribute(gat_fused_kernel, cudaFuncAttributeMaxDynamicSharedMemorySize,
                         SMEM_TOTAL);

    prep_weights<<<512, 256>>>(Wq, Wk, Wv, Wo, W1, W2);
    gat_fused_kernel<<<nCTA, THREADS, SMEM_TOTAL>>>(tokens, bq, bk, bv, bo, g1, be1,
                                                    g2, be2, bf1, bf2, out, nBatch);
}